// round 8
// baseline (speedup 1.0000x reference)
#include <cuda_runtime.h>
#include <cuda_fp16.h>

#define NCH 256

// fp16 NHWC copies of the three feature maps.
// offsets (halves): L1=0, L2=33554432, L3=41943040, total 44040192 (88MB)
__device__ __half g_nhwc[44040192];

// ---------------------------------------------------------------------------
// NCHW fp32 -> NHWC fp16 transpose, pack-at-load version.
// Tile = 32 cells x 64 channels. Load phase: each thread loads channel PAIRS
// (2 LDG.32, same cell), packs to half2, stores one STS.32 into pitch-33 smem
// (bank = (lane+pair)&31: conflict-free). Store phase: 4 LDS.32 (bank =
// (cell+4o+k)&31: conflict-free) + one STG.128 of 8 channels.
__global__ void __launch_bounds__(256)
nchw_to_nhwc_fp16(const float* __restrict__ feat, size_t dst_off, int HW)
{
    __shared__ unsigned tile[32 * 33 + 1];   // half2-packed, pitch 33
    int cell0 = blockIdx.x * 32;
    int c0    = blockIdx.y * 64;
    int b     = blockIdx.z;
    int lane = threadIdx.x & 31;             // cell within tile
    int grp  = threadIdx.x >> 5;             // 0..7
    const float* src = feat + ((size_t)b * NCH + c0) * HW + cell0;
#pragma unroll
    for (int k = 0; k < 4; k++) {
        int pair = k * 8 + grp;              // 0..31 channel pair
        float lo = __ldg(src + (size_t)(2 * pair)     * HW + lane);
        float hi = __ldg(src + (size_t)(2 * pair + 1) * HW + lane);
        __half2 h = __floats2half2_rn(lo, hi);
        tile[lane * 33 + pair] = *(unsigned*)&h;
    }
    __syncthreads();
    int cell = threadIdx.x >> 3;             // 0..31
    int o    = threadIdx.x & 7;              // channel octet (8 ch)
    uint4 u;
    u.x = tile[cell * 33 + 4 * o + 0];
    u.y = tile[cell * 33 + 4 * o + 1];
    u.z = tile[cell * 33 + 4 * o + 2];
    u.w = tile[cell * 33 + 4 * o + 3];
    size_t addr = ((size_t)b * HW + cell0 + cell) * NCH + c0 + o * 8;
    reinterpret_cast<uint4*>(g_nhwc + dst_off)[addr >> 3] = u;
}

// ---------------------------------------------------------------------------
// Gather: one warp = one output pixel, lanes cover 256 channels (8 fp16 each;
// one 16B load per tap). Each bilinear sample accumulates its 4 taps in a
// statically-indexed half2 chain ch[s][*] (HMUL2 first tap, then HFMA2);
// chains combine via HADD2 tree; widened to fp32 once per pixel.

#define TAP0(ptr, wh, s) do {                                                \
    uint4 _v = __ldg(reinterpret_cast<const uint4*>(ptr));                   \
    const __half2* _h = reinterpret_cast<const __half2*>(&_v);               \
    ch[s][0] = __hmul2(wh, _h[0]); ch[s][1] = __hmul2(wh, _h[1]);            \
    ch[s][2] = __hmul2(wh, _h[2]); ch[s][3] = __hmul2(wh, _h[3]);            \
} while (0)

#define TAPH(ptr, wh, s) do {                                                \
    uint4 _v = __ldg(reinterpret_cast<const uint4*>(ptr));                   \
    const __half2* _h = reinterpret_cast<const __half2*>(&_v);               \
    ch[s][0] = __hfma2(wh, _h[0], ch[s][0]);                                 \
    ch[s][1] = __hfma2(wh, _h[1], ch[s][1]);                                 \
    ch[s][2] = __hfma2(wh, _h[2], ch[s][2]);                                 \
    ch[s][3] = __hfma2(wh, _h[3], ch[s][3]);                                 \
} while (0)

template <int P, int H, int W>
__device__ __forceinline__ void gather_level(
    const float* __restrict__ rois, float* __restrict__ out_lvl,
    size_t lvl_off, float scale, int pxbase, int npx, float* __restrict__ sacc)
{
    constexpr int pixels = P * P;
    int tid  = threadIdx.x;
    int wid  = tid >> 5;
    int lane = tid & 31;

    for (int j = 0; j < 4; j++) {
        int pxl = j * 8 + wid;
        int gpx = pxbase + pxl;
        float accf[8] = {0.f,0.f,0.f,0.f,0.f,0.f,0.f,0.f};
        if (gpx < npx) {
            int n  = gpx / pixels;
            int p  = gpx - n * pixels;
            int ph = p / P;
            int pw = p - ph * P;
            const float* r = rois + n * 5;
            int   bi = (int)r[0];
            float x1 = fmaf(r[1], scale, -0.5f);
            float y1 = fmaf(r[2], scale, -0.5f);
            float bw = (fmaf(r[3], scale, -0.5f) - x1) * (1.0f / (float)P);
            float bh = (fmaf(r[4], scale, -0.5f) - y1) * (1.0f / (float)P);
            const __half* img = g_nhwc + lvl_off
                              + (size_t)bi * ((size_t)H * W) * NCH + lane * 8;

            __half2 ch[4][4];
#pragma unroll
            for (int s = 0; s < 4; s++) {
                int iy = s >> 1, ix = s & 1;
                float yy = fmaf((float)ph + 0.25f + 0.5f * iy, bh, y1);
                float xx = fmaf((float)pw + 0.25f + 0.5f * ix, bw, x1);
                bool valid = (yy > -1.f) && (yy < (float)H) &&
                             (xx > -1.f) && (xx < (float)W);
                float yc = fminf(fmaxf(yy, 0.f), (float)(H - 1));
                float xc = fminf(fmaxf(xx, 0.f), (float)(W - 1));
                int y0 = (int)yc;
                int x0 = (int)xc;
                float wy1 = (y0 >= H - 1) ? 1.f : yc - (float)y0;
                float wx1 = (x0 >= W - 1) ? 1.f : xc - (float)x0;
                int ya = min(y0, H - 2);
                int xa = min(x0, W - 2);
                float ws  = valid ? 0.25f : 0.f;
                __half2 w00 = __float2half2_rn((1.f - wy1) * (1.f - wx1) * ws);
                __half2 w01 = __float2half2_rn((1.f - wy1) * wx1 * ws);
                __half2 w10 = __float2half2_rn(wy1 * (1.f - wx1) * ws);
                __half2 w11 = __float2half2_rn(wy1 * wx1 * ws);
                const __half* f = img + (size_t)(ya * W + xa) * NCH;
                TAP0(f,                       w00, s);
                TAPH(f + NCH,                 w01, s);
                TAPH(f + (size_t)W * NCH,     w10, s);
                TAPH(f + (size_t)(W+1) * NCH, w11, s);
            }
#pragma unroll
            for (int rgi = 0; rgi < 4; rgi++) {
                __half2 u = __hadd2(ch[0][rgi], ch[1][rgi]);
                __half2 v = __hadd2(ch[2][rgi], ch[3][rgi]);
                __half2 t = __hadd2(u, v);
                accf[rgi * 2 + 0] = __low2float(t);
                accf[rgi * 2 + 1] = __high2float(t);
            }
        }
        int col = pxl ^ lane;
#pragma unroll
        for (int i = 0; i < 8; i++)
            sacc[(lane * 8 + i) * 32 + col] = accf[i];
    }
    __syncthreads();

    int pxlane = tid & 31;
    int gpx = pxbase + pxlane;
    if (gpx < npx) {
        int n = gpx / pixels;
        int p = gpx - n * pixels;
        float* ob = out_lvl + (size_t)n * NCH * pixels + p;
        int c0i = (tid >> 5) * 32;
#pragma unroll
        for (int i = 0; i < 32; i++) {
            int c = c0i + i;
            ob[(size_t)c * pixels] = sacc[c * 32 + (pxlane ^ ((c >> 3) & 31))];
        }
    }
}

__global__ void __launch_bounds__(256, 6)
roi_gather_kernel(const float* __restrict__ rois, float* __restrict__ out,
                  int N, int nb1, int nb2)
{
    __shared__ float sacc[NCH * 32];
    int blk = blockIdx.x;
    if (blk < nb1) {
        gather_level<28, 256, 256>(rois, out, 0ull, 0.25f,
                                   blk * 32, N * 784, sacc);
    } else if (blk < nb1 + nb2) {
        float* o2 = out + (size_t)N * NCH * 784;
        gather_level<14, 128, 128>(rois, o2, 33554432ull, 0.125f,
                                   (blk - nb1) * 32, N * 196, sacc);
    } else {
        float* o3 = out + (size_t)N * NCH * (784 + 196);
        gather_level<7, 64, 64>(rois, o3, 41943040ull, 0.0625f,
                                (blk - nb1 - nb2) * 32, N * 49, sacc);
    }
}

// ---------------------------------------------------------------------------
extern "C" void kernel_launch(void* const* d_in, const int* in_sizes, int n_in,
                              void* d_out, int out_size)
{
    const float* feat1 = (const float*)d_in[0];  // (2,256,256,256)
    const float* feat2 = (const float*)d_in[1];  // (2,256,128,128)
    const float* feat3 = (const float*)d_in[2];  // (2,256,64,64)
    const float* rois  = (const float*)d_in[3];  // (N,5)
    float* out = (float*)d_out;

    const int N = in_sizes[3] / 5;

    // 1) transpose each level to fp16 NHWC scratch
    {
        dim3 g1(65536 / 32, 4, 2);
        nchw_to_nhwc_fp16<<<g1, 256>>>(feat1, 0ull, 65536);
        dim3 g2(16384 / 32, 4, 2);
        nchw_to_nhwc_fp16<<<g2, 256>>>(feat2, 33554432ull, 16384);
        dim3 g3(4096 / 32, 4, 2);
        nchw_to_nhwc_fp16<<<g3, 256>>>(feat3, 41943040ull, 4096);
    }

    // 2) fused gather over all three levels
    int nb1 = (N * 784 + 31) / 32;
    int nb2 = (N * 196 + 31) / 32;
    int nb3 = (N * 49  + 31) / 32;
    roi_gather_kernel<<<nb1 + nb2 + nb3, 256>>>(rois, out, N, nb1, nb2);
}